// round 6
// baseline (speedup 1.0000x reference)
#include <cuda_runtime.h>

// ---------------------------------------------------------------------------
// DecoderBlock: conv3x3(64->3) + bias + tanh  -> ll [16,3,128,128]
// then two fused inverse Haar levels          -> out [16,3,512,512]
// ---------------------------------------------------------------------------

#define NB   16
#define CIN  64
#define HH   128
#define WW   128
#define HW   (HH * WW)

__device__ float g_ll[NB * 3 * HH * WW];   // 3 MB intermediate

typedef unsigned long long ull;

__device__ __forceinline__ ull pack2(float lo, float hi) {
    ull r;
    asm("mov.b64 %0, {%1, %2};" : "=l"(r) : "f"(lo), "f"(hi));
    return r;
}
__device__ __forceinline__ void unpack2(ull v, float& lo, float& hi) {
    asm("mov.b64 {%0, %1}, %2;" : "=f"(lo), "=f"(hi) : "l"(v));
}
// packed dual-fp32 FMA (sm_100+): d = a*b+c on both 32-bit halves
__device__ __forceinline__ ull fma2(ull a, ull b, ull c) {
    ull d;
    asm("fma.rn.f32x2 %0, %1, %2, %3;" : "=l"(d) : "l"(a), "l"(b), "l"(c));
    return d;
}

// ---------------------------------------------------------------------------
// Kernel A: streaming conv 3x3 pad1, 64->3 + bias + tanh, dual-issue fp32.
// Thread = 1 row x 2 cols x 3 outch (1 f32x2 accumulator per outch).
// CTA (64,4) = 256 threads covers 128 cols x 4 rows. Grid 32x16 = 512 CTAs
// -> 131k threads, ~28 warps/SM. Weights pre-duplicated {w,w} in smem.
// ---------------------------------------------------------------------------
__global__ __launch_bounds__(256) void conv_tanh_kernel(
    const float* __restrict__ fused,
    const float* __restrict__ conv_w,
    const float* __restrict__ conv_b)
{
    // packed weights: [c][o][12] ull (9 used + pad), 16B-aligned strides
    __shared__ ulonglong2 s_w2[CIN * 18];          // 18432 B
    ull* s_w = reinterpret_cast<ull*>(s_w2);

    const int tx  = threadIdx.x;                   // 0..63 -> cols 2tx,2tx+1
    const int ty  = threadIdx.y;                   // 0..3
    const int tid = ty * 64 + tx;
    const int b   = blockIdx.y;
    const int gy  = blockIdx.x * 4 + ty;           // output row

    for (int i = tid; i < CIN * 27; i += 256) {
        int c = i / 27, r = i % 27;
        float w = conv_w[(r / 9) * (CIN * 9) + c * 9 + (r % 9)];
        s_w[c * 36 + (r / 9) * 12 + (r % 9)] = pack2(w, w);
    }
    __syncthreads();

    const bool vtop = (gy > 0);
    const bool vbot = (gy < HH - 1);
    const bool vl   = (tx > 0);
    const bool vr   = (tx < 63);
    const float* p0 = fused + (long)b * CIN * HW + (gy - 1) * WW + 2 * tx;

    // raw input patch: 3 rows x 4 cols {left, m0, m1, right}
    float x0[3][4], x1[3][4];
    auto loadch = [&](int c, float (&x)[3][4]) {
        const bool rv[3] = { vtop, true, vbot };
#pragma unroll
        for (int k = 0; k < 3; k++) {
            const float* rp = p0 + c * HW + k * WW;
            float2 m = make_float2(0.f, 0.f);
            float l = 0.f, r = 0.f;
            if (rv[k]) {
                m = __ldg(reinterpret_cast<const float2*>(rp));
                if (vl) l = __ldg(rp - 1);
                if (vr) r = __ldg(rp + 2);
            }
            x[k][0] = l; x[k][1] = m.x; x[k][2] = m.y; x[k][3] = r;
        }
    };

    ull acc[3];
    acc[0] = acc[1] = acc[2] = pack2(0.f, 0.f);

    auto compute = [&](int c, float (&x)[3][4]) {
        // packed input pairs per row: (x0,x1) (x1,x2) (x2,x3)
        ull xs[3][3];
#pragma unroll
        for (int k = 0; k < 3; k++) {
            xs[k][0] = pack2(x[k][0], x[k][1]);
            xs[k][1] = pack2(x[k][1], x[k][2]);
            xs[k][2] = pack2(x[k][2], x[k][3]);
        }
        const ulonglong2* wp = &s_w2[c * 18];
#pragma unroll
        for (int o = 0; o < 3; o++) {
            ulonglong2 a0 = wp[o * 6 + 0];
            ulonglong2 a1 = wp[o * 6 + 1];
            ulonglong2 a2 = wp[o * 6 + 2];
            ulonglong2 a3 = wp[o * 6 + 3];
            ulonglong2 a4 = wp[o * 6 + 4];
            ull a = acc[o];
            a = fma2(a0.x, xs[0][0], a);
            a = fma2(a0.y, xs[0][1], a);
            a = fma2(a1.x, xs[0][2], a);
            a = fma2(a1.y, xs[1][0], a);
            a = fma2(a2.x, xs[1][1], a);
            a = fma2(a2.y, xs[1][2], a);
            a = fma2(a3.x, xs[2][0], a);
            a = fma2(a3.y, xs[2][1], a);
            a = fma2(a4.x, xs[2][2], a);
            acc[o] = a;
        }
    };

    loadch(0, x0);
#pragma unroll 1
    for (int c = 0; c < CIN; c += 2) {
        loadch(c + 1, x1);
        compute(c, x0);
        if (c + 2 < CIN) loadch(c + 2, x0);
        compute(c + 1, x1);
    }

    const int obase = (b * 3) * HW + gy * WW + 2 * tx;
#pragma unroll
    for (int o = 0; o < 3; o++) {
        const float bias = conv_b[o];
        float lo, hi;
        unpack2(acc[o], lo, hi);
        float2 v;
        v.x = tanhf(lo + bias);
        v.y = tanhf(hi + bias);
        *reinterpret_cast<float2*>(&g_ll[obase + o * HW]) = v;
    }
}

// ---------------------------------------------------------------------------
// Kernel B: fused double inverse Haar (15.1us version).
// ---------------------------------------------------------------------------
__global__ __launch_bounds__(256) void iwt2_kernel(
    const float* __restrict__ hf1,
    const float* __restrict__ hf2,
    float* __restrict__ out)
{
    const int w0 = threadIdx.x;                        // 0..127
    const int h0 = blockIdx.x * 2 + threadIdx.y;       // 0..127
    const int z  = blockIdx.y;                         // b*3 + c
    const int b  = z / 3;
    const int c  = z - b * 3;

    const float a = g_ll[(z * HH + h0) * WW + w0];

    const int hf2base = ((b * 9 + 3 * c) * HH + h0) * WW + w0;
    const float lh = 2.0f * __ldg(&hf2[hf2base            ]) - 1.0f;
    const float hl = 2.0f * __ldg(&hf2[hf2base + HH * WW  ]) - 1.0f;
    const float hh = 2.0f * __ldg(&hf2[hf2base + 2*HH*WW  ]) - 1.0f;

    float cur[2][2];
    cur[0][0] = 0.5f * (a - lh - hl + hh);
    cur[0][1] = 0.5f * (a - lh + hl - hh);
    cur[1][0] = 0.5f * (a + lh - hl - hh);
    cur[1][1] = 0.5f * (a + lh + hl + hh);

    const int h1 = 2 * h0;
    const int w1 = 2 * w0;
    float2 v[3][2];
#pragma unroll
    for (int k = 0; k < 3; k++) {
#pragma unroll
        for (int p0 = 0; p0 < 2; p0++) {
            const float2* ptr = reinterpret_cast<const float2*>(
                &hf1[((b * 9 + 3 * c + k) * 256 + (h1 + p0)) * 256 + w1]);
            v[k][p0] = __ldg(ptr);
        }
    }

    float o16[4][4];
#pragma unroll
    for (int p0 = 0; p0 < 2; p0++) {
#pragma unroll
        for (int q0 = 0; q0 < 2; q0++) {
            const float a2  = cur[p0][q0];
            const float lh1 = 2.0f * (q0 == 0 ? v[0][p0].x : v[0][p0].y) - 1.0f;
            const float hl1 = 2.0f * (q0 == 0 ? v[1][p0].x : v[1][p0].y) - 1.0f;
            const float hh1 = 2.0f * (q0 == 0 ? v[2][p0].x : v[2][p0].y) - 1.0f;
            o16[2 * p0 + 0][2 * q0 + 0] = 0.5f * (a2 - lh1 - hl1 + hh1);
            o16[2 * p0 + 0][2 * q0 + 1] = 0.5f * (a2 - lh1 + hl1 - hh1);
            o16[2 * p0 + 1][2 * q0 + 0] = 0.5f * (a2 + lh1 - hl1 - hh1);
            o16[2 * p0 + 1][2 * q0 + 1] = 0.5f * (a2 + lh1 + hl1 + hh1);
        }
    }

#pragma unroll
    for (int r = 0; r < 4; r++) {
        float4 row;
        row.x = o16[r][0]; row.y = o16[r][1];
        row.z = o16[r][2]; row.w = o16[r][3];
        *reinterpret_cast<float4*>(
            &out[((long)z * 512 + (4 * h0 + r)) * 512 + 4 * w0]) = row;
    }
}

// ---------------------------------------------------------------------------
extern "C" void kernel_launch(void* const* d_in, const int* in_sizes, int n_in,
                              void* d_out, int out_size)
{
    const float* fused  = (const float*)d_in[0];
    const float* hf1    = (const float*)d_in[1];
    const float* hf2    = (const float*)d_in[2];
    const float* conv_w = (const float*)d_in[3];
    const float* conv_b = (const float*)d_in[4];
    float* out = (float*)d_out;

    dim3 cb(64, 4);
    dim3 cg(HH / 4, NB);                    // (32,16) = 512 CTAs
    conv_tanh_kernel<<<cg, cb>>>(fused, conv_w, conv_b);

    dim3 ib(128, 2);
    dim3 ig(HH / 2, NB * 3);                // (64,48) = 3072 CTAs
    iwt2_kernel<<<ig, ib>>>(hf1, hf2, out);
}

// round 7
// speedup vs baseline: 1.8745x; 1.8745x over previous
#include <cuda_runtime.h>

// ---------------------------------------------------------------------------
// DecoderBlock: conv3x3(64->3) + bias + tanh  -> ll [16,3,128,128]
// then two fused inverse Haar levels          -> out [16,3,512,512]
//
// R7: split-K conv (2 slices of 32 input channels, partial sums in gmem),
//     combine + bias + tanh fused into the iwt2 kernel.
// ---------------------------------------------------------------------------

#define NB   16
#define CIN  64
#define KSPLIT 2
#define KCH  (CIN / KSPLIT)     // 32 channels per CTA
#define HH   128
#define WW   128
#define HW   (HH * WW)

// partial conv sums: [kslice][b][o][h][w] = 2 * 3 MB
__device__ float g_part[KSPLIT * NB * 3 * HW];

// ---------------------------------------------------------------------------
// Kernel A: streaming conv 3x3 pad1, split-K partial sums (no bias/tanh).
// Thread = 1 row x 4 cols x 3 outch. CTA (32,4) = 128 threads covers a
// 128-wide x 4-row band. Grid (32, 16, 2) = 1024 CTAs -> ~2x warps/SM vs R3.
// ---------------------------------------------------------------------------
__global__ __launch_bounds__(128) void conv_part_kernel(
    const float* __restrict__ fused,
    const float* __restrict__ conv_w)
{
    __shared__ float s_w[KCH * 32];   // 4 KB, [c][o*9+t] padded to 32

    const int tx  = threadIdx.x;              // 0..31 -> cols 4tx..4tx+3
    const int ty  = threadIdx.y;              // 0..3
    const int tid = ty * 32 + tx;
    const int b   = blockIdx.y;
    const int ks  = blockIdx.z;               // k-slice 0/1
    const int kbase = ks * KCH;
    const int gy  = blockIdx.x * 4 + ty;      // output row 0..127

    // stage this slice's weights: s_w[c*32 + o*9 + t] (src [o][cin][3][3])
    for (int i = tid; i < KCH * 27; i += 128) {
        int c = i / 27, r = i % 27;
        s_w[c * 32 + r] =
            conv_w[(r / 9) * (CIN * 9) + (kbase + c) * 9 + (r % 9)];
    }
    __syncthreads();

    const bool vtop = (gy > 0);
    const bool vbot = (gy < HH - 1);
    const bool vl   = (tx > 0);
    const bool vr   = (tx < 31);
    // base at (channel kbase, row gy-1, col 4tx)
    const float* p0 = fused + (long)b * CIN * HW + (long)kbase * HW
                            + (gy - 1) * WW + 4 * tx;

    float x0[3][6], x1[3][6];

    auto loadch = [&](int c, float (&x)[3][6]) {
        const bool rv[3] = { vtop, true, vbot };
#pragma unroll
        for (int k = 0; k < 3; k++) {
            const float* rp = p0 + c * HW + k * WW;
            float4 m = make_float4(0.f, 0.f, 0.f, 0.f);
            float l = 0.f, r = 0.f;
            if (rv[k]) {
                m = __ldg(reinterpret_cast<const float4*>(rp));
                if (vl) l = __ldg(rp - 1);
                if (vr) r = __ldg(rp + 4);
            }
            x[k][0] = l;   x[k][1] = m.x; x[k][2] = m.y;
            x[k][3] = m.z; x[k][4] = m.w; x[k][5] = r;
        }
    };

    float acc[3][4];
#pragma unroll
    for (int o = 0; o < 3; o++)
#pragma unroll
        for (int q = 0; q < 4; q++) acc[o][q] = 0.0f;

    auto compute = [&](int c, float (&x)[3][6]) {
        float4 w4[8];
#pragma unroll
        for (int k = 0; k < 8; k++)
            w4[k] = *reinterpret_cast<const float4*>(&s_w[c * 32 + 4 * k]);
        const float* w = reinterpret_cast<const float*>(w4);
#pragma unroll
        for (int o = 0; o < 3; o++)
#pragma unroll
            for (int ky = 0; ky < 3; ky++)
#pragma unroll
                for (int kx = 0; kx < 3; kx++) {
                    const float wv = w[o * 9 + ky * 3 + kx];
#pragma unroll
                    for (int q = 0; q < 4; q++)
                        acc[o][q] += wv * x[ky][q + kx];
                }
    };

    loadch(0, x0);
#pragma unroll 1
    for (int c = 0; c < KCH; c += 2) {
        loadch(c + 1, x1);
        compute(c, x0);
        if (c + 2 < KCH) loadch(c + 2, x0);
        compute(c + 1, x1);
    }

    // raw partial sums, one float4 per out channel
    float* pp = &g_part[(long)ks * NB * 3 * HW];
#pragma unroll
    for (int o = 0; o < 3; o++) {
        float4 v;
        v.x = acc[o][0]; v.y = acc[o][1]; v.z = acc[o][2]; v.w = acc[o][3];
        *reinterpret_cast<float4*>(
            &pp[((b * 3 + o) * HH + gy) * WW + 4 * tx]) = v;
    }
}

// ---------------------------------------------------------------------------
// Kernel B: combine(partials)+bias+tanh fused with double inverse Haar.
// One thread per coarse pixel: ll = tanh(p0+p1+bias); level-1 with hf2 ->
// 2x2; level-2 with hf1 -> 4x4 output block (4 float4 rows).
// ---------------------------------------------------------------------------
__global__ __launch_bounds__(256) void iwt2_kernel(
    const float* __restrict__ hf1,
    const float* __restrict__ hf2,
    const float* __restrict__ conv_b,
    float* __restrict__ out)
{
    const int w0 = threadIdx.x;                        // 0..127
    const int h0 = blockIdx.x * 2 + threadIdx.y;       // 0..127
    const int z  = blockIdx.y;                         // b*3 + c
    const int b  = z / 3;
    const int c  = z - b * 3;

    const int llidx = (z * HH + h0) * WW + w0;
    const float a = tanhf(g_part[llidx] + g_part[NB * 3 * HW + llidx]
                          + __ldg(&conv_b[c]));

    const int hf2base = ((b * 9 + 3 * c) * HH + h0) * WW + w0;
    const float lh = 2.0f * __ldg(&hf2[hf2base            ]) - 1.0f;
    const float hl = 2.0f * __ldg(&hf2[hf2base + HH * WW  ]) - 1.0f;
    const float hh = 2.0f * __ldg(&hf2[hf2base + 2*HH*WW  ]) - 1.0f;

    float cur[2][2];
    cur[0][0] = 0.5f * (a - lh - hl + hh);
    cur[0][1] = 0.5f * (a - lh + hl - hh);
    cur[1][0] = 0.5f * (a + lh - hl - hh);
    cur[1][1] = 0.5f * (a + lh + hl + hh);

    const int h1 = 2 * h0;
    const int w1 = 2 * w0;
    float2 v[3][2];
#pragma unroll
    for (int k = 0; k < 3; k++) {
#pragma unroll
        for (int p0 = 0; p0 < 2; p0++) {
            const float2* ptr = reinterpret_cast<const float2*>(
                &hf1[((b * 9 + 3 * c + k) * 256 + (h1 + p0)) * 256 + w1]);
            v[k][p0] = __ldg(ptr);
        }
    }

    float o16[4][4];
#pragma unroll
    for (int p0 = 0; p0 < 2; p0++) {
#pragma unroll
        for (int q0 = 0; q0 < 2; q0++) {
            const float a2  = cur[p0][q0];
            const float lh1 = 2.0f * (q0 == 0 ? v[0][p0].x : v[0][p0].y) - 1.0f;
            const float hl1 = 2.0f * (q0 == 0 ? v[1][p0].x : v[1][p0].y) - 1.0f;
            const float hh1 = 2.0f * (q0 == 0 ? v[2][p0].x : v[2][p0].y) - 1.0f;
            o16[2 * p0 + 0][2 * q0 + 0] = 0.5f * (a2 - lh1 - hl1 + hh1);
            o16[2 * p0 + 0][2 * q0 + 1] = 0.5f * (a2 - lh1 + hl1 - hh1);
            o16[2 * p0 + 1][2 * q0 + 0] = 0.5f * (a2 + lh1 - hl1 - hh1);
            o16[2 * p0 + 1][2 * q0 + 1] = 0.5f * (a2 + lh1 + hl1 + hh1);
        }
    }

#pragma unroll
    for (int r = 0; r < 4; r++) {
        float4 row;
        row.x = o16[r][0]; row.y = o16[r][1];
        row.z = o16[r][2]; row.w = o16[r][3];
        *reinterpret_cast<float4*>(
            &out[((long)z * 512 + (4 * h0 + r)) * 512 + 4 * w0]) = row;
    }
}

// ---------------------------------------------------------------------------
extern "C" void kernel_launch(void* const* d_in, const int* in_sizes, int n_in,
                              void* d_out, int out_size)
{
    const float* fused  = (const float*)d_in[0];
    const float* hf1    = (const float*)d_in[1];
    const float* hf2    = (const float*)d_in[2];
    const float* conv_w = (const float*)d_in[3];
    const float* conv_b = (const float*)d_in[4];
    float* out = (float*)d_out;

    dim3 cb(32, 4);
    dim3 cg(HH / 4, NB, KSPLIT);            // (32,16,2) = 1024 CTAs
    conv_part_kernel<<<cg, cb>>>(fused, conv_w);

    dim3 ib(128, 2);
    dim3 ig(HH / 2, NB * 3);                // (64,48) = 3072 CTAs
    iwt2_kernel<<<ig, ib>>>(hf1, hf2, conv_b, out);
}